// round 7
// baseline (speedup 1.0000x reference)
#include <cuda_runtime.h>

#define BATCH 65536
#define TSTEPS 32
#define F 33
#define H 24

// Scratch for x_spatial [B, 90, 12] (row-major, contiguous per sample).
__device__ __align__(16) float g_xsp[(size_t)BATCH * 1080];

// ---------------------------------------------------------------------------
// Kernel A: conv1+bn1+relu -> conv2+bn2+relu, producing x_spatial[b][s][c].
// One thread per (b, s): reads x[4s-4 .. 4s+4], writes 12 channels.
// ---------------------------------------------------------------------------
__global__ __launch_bounds__(256) void conv_kernel(
    const float* __restrict__ x,
    const float* __restrict__ w1, const float* __restrict__ cb1,
    const float* __restrict__ g1, const float* __restrict__ bb1,
    const float* __restrict__ m1, const float* __restrict__ v1,
    const float* __restrict__ w2, const float* __restrict__ cb2,
    const float* __restrict__ g2, const float* __restrict__ bb2,
    const float* __restrict__ m2, const float* __restrict__ v2)
{
    __shared__ float sw1[30], sw2[216], ss1[6], sbe1[6], ss2[12], sbe2[12];
    int tx = threadIdx.x;
    if (tx < 30)  sw1[tx] = w1[tx];
    if (tx < 216) sw2[tx] = w2[tx];
    if (tx < 6) {
        float sc = g1[tx] * rsqrtf(v1[tx] + 1e-5f);
        ss1[tx]  = sc;
        sbe1[tx] = bb1[tx] + sc * (cb1[tx] - m1[tx]);
    }
    if (tx >= 32 && tx < 44) {
        int c = tx - 32;
        float sc = g2[c] * rsqrtf(v2[c] + 1e-5f);
        ss2[c]  = sc;
        sbe2[c] = bb2[c] + sc * (cb2[c] - m2[c]);
    }
    __syncthreads();

    unsigned gid = blockIdx.x * 256u + (unsigned)tx;   // 0 .. B*90-1 (exact)
    unsigned b = gid / 90u;
    int s = (int)(gid % 90u);

    const float* xb = x + (size_t)b * 360;
    float xv[9];
    int base = 4 * s - 4;
#pragma unroll
    for (int i = 0; i < 9; i++) {
        int idx = base + i;
        xv[i] = (idx >= 0 && idx < 360) ? __ldg(xb + idx) : 0.f;
    }

    // h1 at positions p = 2s-1 .. 2s+1 (conv2 pad=1); p=-1 only at s=0,q=0.
    float h1v[6][3];
#pragma unroll
    for (int q = 0; q < 3; q++) {
        bool valid = (2 * s - 1 + q) >= 0;
#pragma unroll
        for (int c = 0; c < 6; c++) {
            float a = 0.f;
#pragma unroll
            for (int k = 0; k < 5; k++) a = fmaf(sw1[c * 5 + k], xv[2 * q + k], a);
            a = ss1[c] * a + sbe1[c];
            h1v[c][q] = valid ? fmaxf(a, 0.f) : 0.f;
        }
    }

    float* o = g_xsp + (size_t)b * 1080 + s * 12;
#pragma unroll
    for (int c2 = 0; c2 < 12; c2++) {
        float a = 0.f;
#pragma unroll
        for (int c1 = 0; c1 < 6; c1++)
#pragma unroll
            for (int q = 0; q < 3; q++)
                a = fmaf(sw2[(c2 * 6 + c1) * 3 + q], h1v[c1][q], a);
        a = ss2[c2] * a + sbe2[c2];
        o[c2] = fmaxf(a, 0.f);
    }
}

// ---------------------------------------------------------------------------
// Kernel B: LIF x2 + LSTM + head, one thread per sample.
// Spikes packed into a 64-bit mask register (F=33 needs >32 bits!).
// ---------------------------------------------------------------------------
__device__ __forceinline__ float sigf(float x) {
    return __fdividef(1.f, 1.f + __expf(-x));
}
__device__ __forceinline__ float tanhfast(float x) {
    float e = __expf(2.f * x);
    return 1.f - __fdividef(2.f, e + 1.f);   // correct limits at +/-inf
}

__global__ __launch_bounds__(256) void lstm_head_kernel(
    const float* __restrict__ wih, const float* __restrict__ whh,
    const float* __restrict__ bih, const float* __restrict__ bhh,
    const float* __restrict__ rtw1, const float* __restrict__ rtb1,
    const float* __restrict__ rtw2, const float* __restrict__ rtb2,
    const float* __restrict__ fw,  const float* __restrict__ fb,
    const float* __restrict__ cw1, const float* __restrict__ cb1_,
    const float* __restrict__ cw2, const float* __restrict__ cb2_,
    float* __restrict__ out)
{
    // Gate-packed weights: one float4 = {Wi,Wf,Wg,Wo} row element -> LDS.128
    __shared__ float4 sWp[F * 24];     // [k][j]
    __shared__ float4 sHp[24 * 24];    // [k][j]
    __shared__ float4 sBs[24];
    __shared__ float s_rtw1[12 * 36], s_rtb1[12], s_rtw2[24], s_rtb2[2];
    __shared__ float s_fw[24 * 36], s_fb[24];
    __shared__ float s_cw1[12 * 24], s_cb1[12], s_cw2[60], s_cb2[5];

    int tx = threadIdx.x;
    for (int i = tx; i < F * 24; i += 256) {
        int k = i / 24, j = i % 24;
        sWp[i] = make_float4(wih[j * F + k], wih[(24 + j) * F + k],
                             wih[(48 + j) * F + k], wih[(72 + j) * F + k]);
    }
    for (int i = tx; i < 24 * 24; i += 256) {
        int k = i / 24, j = i % 24;
        sHp[i] = make_float4(whh[j * 24 + k], whh[(24 + j) * 24 + k],
                             whh[(48 + j) * 24 + k], whh[(72 + j) * 24 + k]);
    }
    if (tx < 24)
        sBs[tx] = make_float4(bih[tx] + bhh[tx], bih[24 + tx] + bhh[24 + tx],
                              bih[48 + tx] + bhh[48 + tx], bih[72 + tx] + bhh[72 + tx]);
    for (int i = tx; i < 432; i += 256) s_rtw1[i] = rtw1[i];
    if (tx < 12) s_rtb1[tx] = rtb1[tx];
    if (tx < 24) s_rtw2[tx] = rtw2[tx];
    if (tx < 2)  s_rtb2[tx] = rtb2[tx];
    for (int i = tx; i < 864; i += 256) s_fw[i] = fw[i];
    if (tx < 24) s_fb[tx] = fb[tx];
    for (int i = tx; i < 288; i += 256) s_cw1[i] = cw1[i];
    if (tx < 12) s_cb1[tx] = cb1_[tx];
    if (tx < 60) s_cw2[tx] = cw2[tx];
    if (tx < 5)  s_cb2[tx] = cb2_[tx];
    __syncthreads();

    unsigned b = blockIdx.x * 256u + (unsigned)tx;
    const float* fl = g_xsp + (size_t)b * 1080;

    float mem1[F], mem2[F], h[H], c[H];
#pragma unroll
    for (int k = 0; k < F; k++) { mem1[k] = 0.f; mem2[k] = 0.f; }
#pragma unroll
    for (int j = 0; j < H; j++) { h[j] = 0.f; c[j] = 0.f; }

#pragma unroll 1
    for (int t = 0; t < TSTEPS; t++) {
        const float* xt = fl + t * F;
        unsigned long long spmask = 0ull;   // bit k = spike2[k]; F=33 needs 64-bit
#pragma unroll
        for (int k = 0; k < F; k++) {
            float in = __ldg(xt + k);
            float a = 0.95f * mem1[k] + in;
            float s1 = (a > 0.5f) ? 1.f : 0.f;
            mem1[k] = a * (1.f - s1);
            float bm = 0.9f * mem2[k] + s1;
            if (bm > 0.6f) { spmask |= (1ull << k); mem2[k] = 0.f; }
            else mem2[k] = bm;
        }
        float hn[H];
#pragma unroll
        for (int grp = 0; grp < 3; grp++) {
            float4 a[8];
#pragma unroll
            for (int jj = 0; jj < 8; jj++) a[jj] = sBs[grp * 8 + jj];
#pragma unroll
            for (int k = 0; k < F; k++) {
                float f = (float)((unsigned)(spmask >> k) & 1u);
#pragma unroll
                for (int jj = 0; jj < 8; jj++) {
                    float4 w = sWp[k * 24 + grp * 8 + jj];
                    a[jj].x = fmaf(f, w.x, a[jj].x);
                    a[jj].y = fmaf(f, w.y, a[jj].y);
                    a[jj].z = fmaf(f, w.z, a[jj].z);
                    a[jj].w = fmaf(f, w.w, a[jj].w);
                }
            }
#pragma unroll
            for (int k = 0; k < H; k++) {
                float f = h[k];
#pragma unroll
                for (int jj = 0; jj < 8; jj++) {
                    float4 w = sHp[k * 24 + grp * 8 + jj];
                    a[jj].x = fmaf(f, w.x, a[jj].x);
                    a[jj].y = fmaf(f, w.y, a[jj].y);
                    a[jj].z = fmaf(f, w.z, a[jj].z);
                    a[jj].w = fmaf(f, w.w, a[jj].w);
                }
            }
#pragma unroll
            for (int jj = 0; jj < 8; jj++) {
                int j = grp * 8 + jj;
                float gi = sigf(a[jj].x);
                float gf = sigf(a[jj].y);
                float gg = tanhfast(a[jj].z);
                float go = sigf(a[jj].w);
                c[j] = gf * c[j] + gi * gg;
                hn[j] = go * tanhfast(c[j]);
            }
        }
#pragma unroll
        for (int j = 0; j < H; j++) h[j] = hn[j];
    }

    // spatial average over all 90 positions
    float avg[12];
#pragma unroll
    for (int i = 0; i < 12; i++) avg[i] = 0.f;
    const float4* x4 = reinterpret_cast<const float4*>(fl);
#pragma unroll 1
    for (int s = 0; s < 90; s++) {
        float4 a0 = __ldg(x4 + s * 3);
        float4 a1 = __ldg(x4 + s * 3 + 1);
        float4 a2 = __ldg(x4 + s * 3 + 2);
        avg[0] += a0.x; avg[1] += a0.y; avg[2]  += a0.z; avg[3]  += a0.w;
        avg[4] += a1.x; avg[5] += a1.y; avg[6]  += a1.z; avg[7]  += a1.w;
        avg[8] += a2.x; avg[9] += a2.y; avg[10] += a2.z; avg[11] += a2.w;
    }
#pragma unroll
    for (int i = 0; i < 12; i++) avg[i] *= (1.f / 90.f);

    float comb[36];
#pragma unroll
    for (int j = 0; j < 24; j++) comb[j] = h[j];
#pragma unroll
    for (int i = 0; i < 12; i++) comb[24 + i] = avg[i];

    float z1[12];
#pragma unroll
    for (int i = 0; i < 12; i++) {
        float a = s_rtb1[i];
#pragma unroll
        for (int k = 0; k < 36; k++) a = fmaf(s_rtw1[i * 36 + k], comb[k], a);
        z1[i] = fmaxf(a, 0.f);
    }
    float z2[2];
#pragma unroll
    for (int i = 0; i < 2; i++) {
        float a = s_rtb2[i];
#pragma unroll
        for (int k = 0; k < 12; k++) a = fmaf(s_rtw2[i * 12 + k], z1[k], a);
        z2[i] = a;
    }
    float mx = fmaxf(z2[0], z2[1]);
    float e0 = __expf(z2[0] - mx), e1 = __expf(z2[1] - mx);
    float inv = 1.f / (e0 + e1);
    float rw0 = 0.7f * (e0 * inv), rw1 = 0.3f * (e1 * inv);
    float alpha = rw0 / (rw0 + rw1);

    float fin[36];
#pragma unroll
    for (int j = 0; j < 24; j++) fin[j] = h[j] * alpha;
    float om = 1.f - alpha;
#pragma unroll
    for (int i = 0; i < 12; i++) fin[24 + i] = avg[i] * om;

    float fused[24];
#pragma unroll
    for (int i = 0; i < 24; i++) {
        float a = s_fb[i];
#pragma unroll
        for (int k = 0; k < 36; k++) a = fmaf(s_fw[i * 36 + k], fin[k], a);
        fused[i] = fmaxf(a, 0.f);
    }
    float y1[12];
#pragma unroll
    for (int i = 0; i < 12; i++) {
        float a = s_cb1[i];
#pragma unroll
        for (int k = 0; k < 24; k++) a = fmaf(s_cw1[i * 24 + k], fused[k], a);
        y1[i] = fmaxf(a, 0.f);
    }
    float* ob = out + (size_t)b * 5;
#pragma unroll
    for (int i = 0; i < 5; i++) {
        float a = s_cb2[i];
#pragma unroll
        for (int k = 0; k < 12; k++) a = fmaf(s_cw2[i * 12 + k], y1[k], a);
        ob[i] = a;
    }
}

extern "C" void kernel_launch(void* const* d_in, const int* in_sizes, int n_in,
                              void* d_out, int out_size) {
    const float* x   = (const float*)d_in[0];
    const float* c1w = (const float*)d_in[1];
    const float* c1b = (const float*)d_in[2];
    const float* b1g = (const float*)d_in[3];
    const float* b1b = (const float*)d_in[4];
    const float* b1m = (const float*)d_in[5];
    const float* b1v = (const float*)d_in[6];
    const float* c2w = (const float*)d_in[7];
    const float* c2b = (const float*)d_in[8];
    const float* b2g = (const float*)d_in[9];
    const float* b2b = (const float*)d_in[10];
    const float* b2m = (const float*)d_in[11];
    const float* b2v = (const float*)d_in[12];
    const float* wih = (const float*)d_in[13];
    const float* whh = (const float*)d_in[14];
    const float* bih = (const float*)d_in[15];
    const float* bhh = (const float*)d_in[16];
    const float* rtw1 = (const float*)d_in[17];
    const float* rtb1 = (const float*)d_in[18];
    const float* rtw2 = (const float*)d_in[19];
    const float* rtb2 = (const float*)d_in[20];
    const float* fw  = (const float*)d_in[21];
    const float* fb  = (const float*)d_in[22];
    const float* cw1 = (const float*)d_in[23];
    const float* cb1 = (const float*)d_in[24];
    const float* cw2 = (const float*)d_in[25];
    const float* cb2 = (const float*)d_in[26];
    float* out = (float*)d_out;

    // B*90 = 5,898,240 threads -> exactly 23040 blocks of 256
    conv_kernel<<<23040, 256>>>(x, c1w, c1b, b1g, b1b, b1m, b1v,
                                c2w, c2b, b2g, b2b, b2m, b2v);
    // B = 65536 threads -> 256 blocks of 256
    lstm_head_kernel<<<256, 256>>>(wih, whh, bih, bhh,
                                   rtw1, rtb1, rtw2, rtb2,
                                   fw, fb, cw1, cb1, cw2, cb2, out);
}

// round 9
// speedup vs baseline: 1.2990x; 1.2990x over previous
#include <cuda_runtime.h>

#define BATCH 65536
#define TSTEPS 32
#define F 33
#define H 24

// Scratch for x_spatial [B, 90, 12] (row-major, contiguous per sample).
__device__ __align__(16) float g_xsp[(size_t)BATCH * 1080];

// ---------------------------------------------------------------------------
// Kernel A: conv1+bn1+relu -> conv2+bn2+relu, producing x_spatial[b][s][c].
// One thread per (b, s). (Unchanged from the passing R7 version.)
// ---------------------------------------------------------------------------
__global__ __launch_bounds__(256) void conv_kernel(
    const float* __restrict__ x,
    const float* __restrict__ w1, const float* __restrict__ cb1,
    const float* __restrict__ g1, const float* __restrict__ bb1,
    const float* __restrict__ m1, const float* __restrict__ v1,
    const float* __restrict__ w2, const float* __restrict__ cb2,
    const float* __restrict__ g2, const float* __restrict__ bb2,
    const float* __restrict__ m2, const float* __restrict__ v2)
{
    __shared__ float sw1[30], sw2[216], ss1[6], sbe1[6], ss2[12], sbe2[12];
    int tx = threadIdx.x;
    if (tx < 30)  sw1[tx] = w1[tx];
    if (tx < 216) sw2[tx] = w2[tx];
    if (tx < 6) {
        float sc = g1[tx] * rsqrtf(v1[tx] + 1e-5f);
        ss1[tx]  = sc;
        sbe1[tx] = bb1[tx] + sc * (cb1[tx] - m1[tx]);
    }
    if (tx >= 32 && tx < 44) {
        int c = tx - 32;
        float sc = g2[c] * rsqrtf(v2[c] + 1e-5f);
        ss2[c]  = sc;
        sbe2[c] = bb2[c] + sc * (cb2[c] - m2[c]);
    }
    __syncthreads();

    unsigned gid = blockIdx.x * 256u + (unsigned)tx;   // 0 .. B*90-1 (exact)
    unsigned b = gid / 90u;
    int s = (int)(gid % 90u);

    const float* xb = x + (size_t)b * 360;
    float xv[9];
    int base = 4 * s - 4;
#pragma unroll
    for (int i = 0; i < 9; i++) {
        int idx = base + i;
        xv[i] = (idx >= 0 && idx < 360) ? __ldg(xb + idx) : 0.f;
    }

    float h1v[6][3];
#pragma unroll
    for (int q = 0; q < 3; q++) {
        bool valid = (2 * s - 1 + q) >= 0;
#pragma unroll
        for (int c = 0; c < 6; c++) {
            float a = 0.f;
#pragma unroll
            for (int k = 0; k < 5; k++) a = fmaf(sw1[c * 5 + k], xv[2 * q + k], a);
            a = ss1[c] * a + sbe1[c];
            h1v[c][q] = valid ? fmaxf(a, 0.f) : 0.f;
        }
    }

    float* o = g_xsp + (size_t)b * 1080 + s * 12;
#pragma unroll
    for (int c2 = 0; c2 < 12; c2++) {
        float a = 0.f;
#pragma unroll
        for (int c1 = 0; c1 < 6; c1++)
#pragma unroll
            for (int q = 0; q < 3; q++)
                a = fmaf(sw2[(c2 * 6 + c1) * 3 + q], h1v[c1][q], a);
        a = ss2[c2] * a + sbe2[c2];
        o[c2] = fmaxf(a, 0.f);
    }
}

// ---------------------------------------------------------------------------
// Kernel B: LIF x2 + LSTM + head. 8 lanes cooperate per sample.
// Lane owns 3 hidden units and features k = lane + 8i. State fits registers.
// ---------------------------------------------------------------------------
__device__ __forceinline__ float sigf(float x) {
    return __fdividef(1.f, 1.f + __expf(-x));
}
__device__ __forceinline__ float tanhfast(float x) {
    float e = __expf(2.f * x);
    return 1.f - __fdividef(2.f, e + 1.f);   // correct limits at +/-inf
}

__global__ __launch_bounds__(256) void lstm_head_kernel(
    const float* __restrict__ wih, const float* __restrict__ whh,
    const float* __restrict__ bih, const float* __restrict__ bhh,
    const float* __restrict__ rtw1, const float* __restrict__ rtb1,
    const float* __restrict__ rtw2, const float* __restrict__ rtb2,
    const float* __restrict__ fw,  const float* __restrict__ fb,
    const float* __restrict__ cw1, const float* __restrict__ cb1_,
    const float* __restrict__ cw2, const float* __restrict__ cb2_,
    float* __restrict__ out)
{
    // Gate-packed weights: float4 = {Wi,Wf,Wg,Wo} at [k][j] -> LDS.128
    __shared__ float4 sWp[F * 24];     // [k][j]
    __shared__ float4 sHp[24 * 24];    // [k][j]
    __shared__ float4 sBs[24];
    __shared__ float s_rtw1[12 * 36], s_rtb1[12], s_rtw2[24], s_rtb2[2];
    __shared__ float s_fw[24 * 36], s_fb[24];
    __shared__ float s_cw1[12 * 24], s_cb1[12], s_cw2[60], s_cb2[5];

    int tx = threadIdx.x;
    for (int i = tx; i < F * 24; i += 256) {
        int k = i / 24, j = i % 24;
        sWp[i] = make_float4(wih[j * F + k], wih[(24 + j) * F + k],
                             wih[(48 + j) * F + k], wih[(72 + j) * F + k]);
    }
    for (int i = tx; i < 24 * 24; i += 256) {
        int k = i / 24, j = i % 24;
        sHp[i] = make_float4(whh[j * 24 + k], whh[(24 + j) * 24 + k],
                             whh[(48 + j) * 24 + k], whh[(72 + j) * 24 + k]);
    }
    if (tx < 24)
        sBs[tx] = make_float4(bih[tx] + bhh[tx], bih[24 + tx] + bhh[24 + tx],
                              bih[48 + tx] + bhh[48 + tx], bih[72 + tx] + bhh[72 + tx]);
    for (int i = tx; i < 432; i += 256) s_rtw1[i] = rtw1[i];
    if (tx < 12) s_rtb1[tx] = rtb1[tx];
    if (tx < 24) s_rtw2[tx] = rtw2[tx];
    if (tx < 2)  s_rtb2[tx] = rtb2[tx];
    for (int i = tx; i < 864; i += 256) s_fw[i] = fw[i];
    if (tx < 24) s_fb[tx] = fb[tx];
    for (int i = tx; i < 288; i += 256) s_cw1[i] = cw1[i];
    if (tx < 12) s_cb1[tx] = cb1_[tx];
    if (tx < 60) s_cw2[tx] = cw2[tx];
    if (tx < 5)  s_cb2[tx] = cb2_[tx];
    __syncthreads();

    unsigned gtid = blockIdx.x * 256u + (unsigned)tx;
    unsigned b = gtid >> 3;            // 8 lanes per sample
    int lane = tx & 7;
    int j0 = lane * 3;                 // this lane's hidden units j0..j0+2
    const float* fl = g_xsp + (size_t)b * 1080;

    // LIF state for owned features k = lane + 8i (lane 0 also owns k=32).
    float mem1[5], mem2[5];
#pragma unroll
    for (int i = 0; i < 5; i++) { mem1[i] = 0.f; mem2[i] = 0.f; }
    float h0 = 0.f, h1 = 0.f, h2 = 0.f;
    float c0 = 0.f, c1 = 0.f, c2 = 0.f;

#pragma unroll 1
    for (int t = 0; t < TSTEPS; t++) {
        const float* xt = fl + t * F;

        // --- LIF for owned features; build partial spike mask ---
        unsigned long long pm = 0ull;
#pragma unroll
        for (int i = 0; i < 5; i++) {
            if (i < 4 || lane == 0) {           // k = lane + 8i < 33
                int k = lane + 8 * i;
                float in = __ldg(xt + k);
                float a = 0.95f * mem1[i] + in;
                float s1 = (a > 0.5f) ? 1.f : 0.f;
                mem1[i] = a * (1.f - s1);
                float bm = 0.9f * mem2[i] + s1;
                if (bm > 0.6f) { pm |= (1ull << k); mem2[i] = 0.f; }
                else mem2[i] = bm;
            }
        }
        // OR-reduce across the 8-lane group -> full mask everywhere
        pm |= __shfl_xor_sync(0xffffffffu, pm, 1, 8);
        pm |= __shfl_xor_sync(0xffffffffu, pm, 2, 8);
        pm |= __shfl_xor_sync(0xffffffffu, pm, 4, 8);

        // --- gates for this lane's 3 hidden units ---
        float4 a0 = sBs[j0], a1 = sBs[j0 + 1], a2 = sBs[j0 + 2];
#pragma unroll
        for (int k = 0; k < F; k++) {
            float f = (float)((unsigned)(pm >> k) & 1u);
            float4 w0 = sWp[k * 24 + j0];
            float4 w1 = sWp[k * 24 + j0 + 1];
            float4 w2 = sWp[k * 24 + j0 + 2];
            a0.x = fmaf(f, w0.x, a0.x); a0.y = fmaf(f, w0.y, a0.y);
            a0.z = fmaf(f, w0.z, a0.z); a0.w = fmaf(f, w0.w, a0.w);
            a1.x = fmaf(f, w1.x, a1.x); a1.y = fmaf(f, w1.y, a1.y);
            a1.z = fmaf(f, w1.z, a1.z); a1.w = fmaf(f, w1.w, a1.w);
            a2.x = fmaf(f, w2.x, a2.x); a2.y = fmaf(f, w2.y, a2.y);
            a2.z = fmaf(f, w2.z, a2.z); a2.w = fmaf(f, w2.w, a2.w);
        }
#pragma unroll
        for (int k = 0; k < H; k++) {
            // h[k] lives on lane k/3, element k%3 (compile-time constants)
            float hk = (k % 3 == 0) ? h0 : (k % 3 == 1) ? h1 : h2;
            float f = __shfl_sync(0xffffffffu, hk, k / 3, 8);
            float4 w0 = sHp[k * 24 + j0];
            float4 w1 = sHp[k * 24 + j0 + 1];
            float4 w2 = sHp[k * 24 + j0 + 2];
            a0.x = fmaf(f, w0.x, a0.x); a0.y = fmaf(f, w0.y, a0.y);
            a0.z = fmaf(f, w0.z, a0.z); a0.w = fmaf(f, w0.w, a0.w);
            a1.x = fmaf(f, w1.x, a1.x); a1.y = fmaf(f, w1.y, a1.y);
            a1.z = fmaf(f, w1.z, a1.z); a1.w = fmaf(f, w1.w, a1.w);
            a2.x = fmaf(f, w2.x, a2.x); a2.y = fmaf(f, w2.y, a2.y);
            a2.z = fmaf(f, w2.z, a2.z); a2.w = fmaf(f, w2.w, a2.w);
        }
        {
            float gi = sigf(a0.x), gf = sigf(a0.y), gg = tanhfast(a0.z), go = sigf(a0.w);
            c0 = gf * c0 + gi * gg;  h0 = go * tanhfast(c0);
            gi = sigf(a1.x); gf = sigf(a1.y); gg = tanhfast(a1.z); go = sigf(a1.w);
            c1 = gf * c1 + gi * gg;  h1 = go * tanhfast(c1);
            gi = sigf(a2.x); gf = sigf(a2.y); gg = tanhfast(a2.z); go = sigf(a2.w);
            c2 = gf * c2 + gi * gg;  h2 = go * tanhfast(c2);
        }
    }

    // --- gather full h into every lane ---
    float comb[36];
#pragma unroll
    for (int k = 0; k < 24; k++) {
        float hk = (k % 3 == 0) ? h0 : (k % 3 == 1) ? h1 : h2;
        comb[k] = __shfl_sync(0xffffffffu, hk, k / 3, 8);
    }

    // --- spatial average: lane sums rows s = lane, lane+8, ... then reduce ---
    float pv[12];
#pragma unroll
    for (int i = 0; i < 12; i++) pv[i] = 0.f;
    const float4* x4 = reinterpret_cast<const float4*>(fl);
#pragma unroll 1
    for (int s = lane; s < 90; s += 8) {
        float4 q0 = __ldg(x4 + s * 3);
        float4 q1 = __ldg(x4 + s * 3 + 1);
        float4 q2 = __ldg(x4 + s * 3 + 2);
        pv[0] += q0.x; pv[1] += q0.y; pv[2]  += q0.z; pv[3]  += q0.w;
        pv[4] += q1.x; pv[5] += q1.y; pv[6]  += q1.z; pv[7]  += q1.w;
        pv[8] += q2.x; pv[9] += q2.y; pv[10] += q2.z; pv[11] += q2.w;
    }
#pragma unroll
    for (int i = 0; i < 12; i++) {
        float v = pv[i];
        v += __shfl_xor_sync(0xffffffffu, v, 1, 8);
        v += __shfl_xor_sync(0xffffffffu, v, 2, 8);
        v += __shfl_xor_sync(0xffffffffu, v, 4, 8);
        comb[24 + i] = v * (1.f / 90.f);
    }

    // --- head (computed redundantly by all 8 lanes of the group) ---
    float z1[12];
#pragma unroll
    for (int i = 0; i < 12; i++) {
        float a = s_rtb1[i];
#pragma unroll
        for (int k = 0; k < 36; k++) a = fmaf(s_rtw1[i * 36 + k], comb[k], a);
        z1[i] = fmaxf(a, 0.f);
    }
    float z2[2];
#pragma unroll
    for (int i = 0; i < 2; i++) {
        float a = s_rtb2[i];
#pragma unroll
        for (int k = 0; k < 12; k++) a = fmaf(s_rtw2[i * 12 + k], z1[k], a);
        z2[i] = a;
    }
    float mx = fmaxf(z2[0], z2[1]);
    float e0 = __expf(z2[0] - mx), e1 = __expf(z2[1] - mx);
    float inv = 1.f / (e0 + e1);
    float rw0 = 0.7f * (e0 * inv), rw1 = 0.3f * (e1 * inv);
    float alpha = rw0 / (rw0 + rw1);
    float om = 1.f - alpha;

    float fin[36];
#pragma unroll
    for (int j = 0; j < 24; j++) fin[j] = comb[j] * alpha;
#pragma unroll
    for (int i = 0; i < 12; i++) fin[24 + i] = comb[24 + i] * om;

    float fused[24];
#pragma unroll
    for (int i = 0; i < 24; i++) {
        float a = s_fb[i];
#pragma unroll
        for (int k = 0; k < 36; k++) a = fmaf(s_fw[i * 36 + k], fin[k], a);
        fused[i] = fmaxf(a, 0.f);
    }
    float y1[12];
#pragma unroll
    for (int i = 0; i < 12; i++) {
        float a = s_cb1[i];
#pragma unroll
        for (int k = 0; k < 24; k++) a = fmaf(s_cw1[i * 24 + k], fused[k], a);
        y1[i] = fmaxf(a, 0.f);
    }
    if (lane == 0) {
        float* ob = out + (size_t)b * 5;
#pragma unroll
        for (int i = 0; i < 5; i++) {
            float a = s_cb2[i];
#pragma unroll
            for (int k = 0; k < 12; k++) a = fmaf(s_cw2[i * 12 + k], y1[k], a);
            ob[i] = a;
        }
    }
}

extern "C" void kernel_launch(void* const* d_in, const int* in_sizes, int n_in,
                              void* d_out, int out_size) {
    const float* x   = (const float*)d_in[0];
    const float* c1w = (const float*)d_in[1];
    const float* c1b = (const float*)d_in[2];
    const float* b1g = (const float*)d_in[3];
    const float* b1b = (const float*)d_in[4];
    const float* b1m = (const float*)d_in[5];
    const float* b1v = (const float*)d_in[6];
    const float* c2w = (const float*)d_in[7];
    const float* c2b = (const float*)d_in[8];
    const float* b2g = (const float*)d_in[9];
    const float* b2b = (const float*)d_in[10];
    const float* b2m = (const float*)d_in[11];
    const float* b2v = (const float*)d_in[12];
    const float* wih = (const float*)d_in[13];
    const float* whh = (const float*)d_in[14];
    const float* bih = (const float*)d_in[15];
    const float* bhh = (const float*)d_in[16];
    const float* rtw1 = (const float*)d_in[17];
    const float* rtb1 = (const float*)d_in[18];
    const float* rtw2 = (const float*)d_in[19];
    const float* rtb2 = (const float*)d_in[20];
    const float* fw  = (const float*)d_in[21];
    const float* fb  = (const float*)d_in[22];
    const float* cw1 = (const float*)d_in[23];
    const float* cb1 = (const float*)d_in[24];
    const float* cw2 = (const float*)d_in[25];
    const float* cb2 = (const float*)d_in[26];
    float* out = (float*)d_out;

    // B*90 = 5,898,240 threads -> exactly 23040 blocks of 256
    conv_kernel<<<23040, 256>>>(x, c1w, c1b, b1g, b1b, b1m, b1v,
                                c2w, c2b, b2g, b2b, b2m, b2v);
    // B*8 = 524,288 threads -> 2048 blocks of 256
    lstm_head_kernel<<<2048, 256>>>(wih, whh, bih, bhh,
                                    rtw1, rtb1, rtw2, rtb2,
                                    fw, fb, cw1, cb1, cw2, cb2, out);
}

// round 10
// speedup vs baseline: 1.8542x; 1.4274x over previous
#include <cuda_runtime.h>

#define BATCH 65536
#define TSTEPS 32
#define F 33
#define H 24

// Scratch for x_spatial [B, 90, 12] (row-major, contiguous per sample).
__device__ __align__(16) float g_xsp[(size_t)BATCH * 1080];
// Spike mask per (sample, timestep): bit k = spike2[k] at step t.
__device__ __align__(16) unsigned long long g_mask[(size_t)BATCH * TSTEPS];

// ---------------------------------------------------------------------------
// Kernel A: conv1+bn1+relu -> conv2+bn2+relu, producing x_spatial[b][s][c].
// (Unchanged from passing R9 version.)
// ---------------------------------------------------------------------------
__global__ __launch_bounds__(256) void conv_kernel(
    const float* __restrict__ x,
    const float* __restrict__ w1, const float* __restrict__ cb1,
    const float* __restrict__ g1, const float* __restrict__ bb1,
    const float* __restrict__ m1, const float* __restrict__ v1,
    const float* __restrict__ w2, const float* __restrict__ cb2,
    const float* __restrict__ g2, const float* __restrict__ bb2,
    const float* __restrict__ m2, const float* __restrict__ v2)
{
    __shared__ float sw1[30], sw2[216], ss1[6], sbe1[6], ss2[12], sbe2[12];
    int tx = threadIdx.x;
    if (tx < 30)  sw1[tx] = w1[tx];
    if (tx < 216) sw2[tx] = w2[tx];
    if (tx < 6) {
        float sc = g1[tx] * rsqrtf(v1[tx] + 1e-5f);
        ss1[tx]  = sc;
        sbe1[tx] = bb1[tx] + sc * (cb1[tx] - m1[tx]);
    }
    if (tx >= 32 && tx < 44) {
        int c = tx - 32;
        float sc = g2[c] * rsqrtf(v2[c] + 1e-5f);
        ss2[c]  = sc;
        sbe2[c] = bb2[c] + sc * (cb2[c] - m2[c]);
    }
    __syncthreads();

    unsigned gid = blockIdx.x * 256u + (unsigned)tx;   // 0 .. B*90-1 (exact)
    unsigned b = gid / 90u;
    int s = (int)(gid % 90u);

    const float* xb = x + (size_t)b * 360;
    float xv[9];
    int base = 4 * s - 4;
#pragma unroll
    for (int i = 0; i < 9; i++) {
        int idx = base + i;
        xv[i] = (idx >= 0 && idx < 360) ? __ldg(xb + idx) : 0.f;
    }

    float h1v[6][3];
#pragma unroll
    for (int q = 0; q < 3; q++) {
        bool valid = (2 * s - 1 + q) >= 0;
#pragma unroll
        for (int c = 0; c < 6; c++) {
            float a = 0.f;
#pragma unroll
            for (int k = 0; k < 5; k++) a = fmaf(sw1[c * 5 + k], xv[2 * q + k], a);
            a = ss1[c] * a + sbe1[c];
            h1v[c][q] = valid ? fmaxf(a, 0.f) : 0.f;
        }
    }

    float* o = g_xsp + (size_t)b * 1080 + s * 12;
#pragma unroll
    for (int c2 = 0; c2 < 12; c2++) {
        float a = 0.f;
#pragma unroll
        for (int c1 = 0; c1 < 6; c1++)
#pragma unroll
            for (int q = 0; q < 3; q++)
                a = fmaf(sw2[(c2 * 6 + c1) * 3 + q], h1v[c1][q], a);
        a = ss2[c2] * a + sbe2[c2];
        o[c2] = fmaxf(a, 0.f);
    }
}

// ---------------------------------------------------------------------------
// Kernel B: double LIF, 8 lanes per sample (lane owns k = lane+8i).
// Emits per-(b,t) 33-bit spike mask as uint64.
// ---------------------------------------------------------------------------
__global__ __launch_bounds__(256) void lif_kernel()
{
    unsigned gtid = blockIdx.x * 256u + threadIdx.x;   // B*8 threads
    unsigned b = gtid >> 3;
    int lane = threadIdx.x & 7;
    const float* fl = g_xsp + (size_t)b * 1080;

    float mem1[5], mem2[5];
#pragma unroll
    for (int i = 0; i < 5; i++) { mem1[i] = 0.f; mem2[i] = 0.f; }

#pragma unroll 1
    for (int t = 0; t < TSTEPS; t++) {
        const float* xt = fl + t * F;
        unsigned long long pm = 0ull;
#pragma unroll
        for (int i = 0; i < 5; i++) {
            if (i < 4 || lane == 0) {           // k = lane + 8i < 33
                int k = lane + 8 * i;
                float in = __ldg(xt + k);
                float a = 0.95f * mem1[i] + in;
                float s1 = (a > 0.5f) ? 1.f : 0.f;
                mem1[i] = a * (1.f - s1);
                float bm = 0.9f * mem2[i] + s1;
                if (bm > 0.6f) { pm |= (1ull << k); mem2[i] = 0.f; }
                else mem2[i] = bm;
            }
        }
        pm |= __shfl_xor_sync(0xffffffffu, pm, 1, 8);
        pm |= __shfl_xor_sync(0xffffffffu, pm, 2, 8);
        pm |= __shfl_xor_sync(0xffffffffu, pm, 4, 8);
        if (lane == 0) g_mask[(size_t)b * TSTEPS + t] = pm;
    }
}

// ---------------------------------------------------------------------------
// Kernel C: LSTM + head. 8 lanes x 2 samples per thread.
// Lane owns hidden units j0..j0+2 of both samples.
// ---------------------------------------------------------------------------
__device__ __forceinline__ float sigf(float x) {
    return __fdividef(1.f, 1.f + __expf(-x));
}
__device__ __forceinline__ float tanhfast(float x) {
    float e = __expf(2.f * x);
    return 1.f - __fdividef(2.f, e + 1.f);   // correct limits at +/-inf
}

__global__ __launch_bounds__(256) void lstm_head_kernel(
    const float* __restrict__ wih, const float* __restrict__ whh,
    const float* __restrict__ bih, const float* __restrict__ bhh,
    const float* __restrict__ rtw1, const float* __restrict__ rtb1,
    const float* __restrict__ rtw2, const float* __restrict__ rtb2,
    const float* __restrict__ fw,  const float* __restrict__ fb,
    const float* __restrict__ cw1, const float* __restrict__ cb1_,
    const float* __restrict__ cw2, const float* __restrict__ cb2_,
    float* __restrict__ out)
{
    __shared__ float4 sWp[F * 24];     // {Wi,Wf,Wg,Wo}[k][j]
    __shared__ float4 sHp[24 * 24];
    __shared__ float4 sBs[24];
    __shared__ float s_rtw1[12 * 36], s_rtb1[12], s_rtw2[24], s_rtb2[2];
    __shared__ float s_fw[24 * 36], s_fb[24];
    __shared__ float s_cw1[12 * 24], s_cb1[12], s_cw2[60], s_cb2[5];

    int tx = threadIdx.x;
    for (int i = tx; i < F * 24; i += 256) {
        int k = i / 24, j = i % 24;
        sWp[i] = make_float4(wih[j * F + k], wih[(24 + j) * F + k],
                             wih[(48 + j) * F + k], wih[(72 + j) * F + k]);
    }
    for (int i = tx; i < 24 * 24; i += 256) {
        int k = i / 24, j = i % 24;
        sHp[i] = make_float4(whh[j * 24 + k], whh[(24 + j) * 24 + k],
                             whh[(48 + j) * 24 + k], whh[(72 + j) * 24 + k]);
    }
    if (tx < 24)
        sBs[tx] = make_float4(bih[tx] + bhh[tx], bih[24 + tx] + bhh[24 + tx],
                              bih[48 + tx] + bhh[48 + tx], bih[72 + tx] + bhh[72 + tx]);
    for (int i = tx; i < 432; i += 256) s_rtw1[i] = rtw1[i];
    if (tx < 12) s_rtb1[tx] = rtb1[tx];
    if (tx < 24) s_rtw2[tx] = rtw2[tx];
    if (tx < 2)  s_rtb2[tx] = rtb2[tx];
    for (int i = tx; i < 864; i += 256) s_fw[i] = fw[i];
    if (tx < 24) s_fb[tx] = fb[tx];
    for (int i = tx; i < 288; i += 256) s_cw1[i] = cw1[i];
    if (tx < 12) s_cb1[tx] = cb1_[tx];
    if (tx < 60) s_cw2[tx] = cw2[tx];
    if (tx < 5)  s_cb2[tx] = cb2_[tx];
    __syncthreads();

    unsigned gtid = blockIdx.x * 256u + (unsigned)tx;
    unsigned grp = gtid >> 3;          // 8 lanes per sample pair
    int lane = tx & 7;
    int j0 = lane * 3;
    unsigned b0 = grp * 2u, b1 = b0 + 1u;

    float hA0 = 0.f, hA1 = 0.f, hA2 = 0.f, cA0 = 0.f, cA1 = 0.f, cA2 = 0.f;
    float hB0 = 0.f, hB1 = 0.f, hB2 = 0.f, cB0 = 0.f, cB1 = 0.f, cB2 = 0.f;

    const unsigned long long* mkA = g_mask + (size_t)b0 * TSTEPS;
    const unsigned long long* mkB = g_mask + (size_t)b1 * TSTEPS;

#pragma unroll 1
    for (int t = 0; t < TSTEPS; t++) {
        unsigned long long ma = __ldg(mkA + t);
        unsigned long long mb = __ldg(mkB + t);

        float4 aA0 = sBs[j0], aA1 = sBs[j0 + 1], aA2 = sBs[j0 + 2];
        float4 aB0 = aA0, aB1 = aA1, aB2 = aA2;
#pragma unroll
        for (int k = 0; k < F; k++) {
            float fa = (float)((unsigned)(ma >> k) & 1u);
            float fb = (float)((unsigned)(mb >> k) & 1u);
            float4 w0 = sWp[k * 24 + j0];
            float4 w1 = sWp[k * 24 + j0 + 1];
            float4 w2 = sWp[k * 24 + j0 + 2];
            aA0.x = fmaf(fa, w0.x, aA0.x); aA0.y = fmaf(fa, w0.y, aA0.y);
            aA0.z = fmaf(fa, w0.z, aA0.z); aA0.w = fmaf(fa, w0.w, aA0.w);
            aA1.x = fmaf(fa, w1.x, aA1.x); aA1.y = fmaf(fa, w1.y, aA1.y);
            aA1.z = fmaf(fa, w1.z, aA1.z); aA1.w = fmaf(fa, w1.w, aA1.w);
            aA2.x = fmaf(fa, w2.x, aA2.x); aA2.y = fmaf(fa, w2.y, aA2.y);
            aA2.z = fmaf(fa, w2.z, aA2.z); aA2.w = fmaf(fa, w2.w, aA2.w);
            aB0.x = fmaf(fb, w0.x, aB0.x); aB0.y = fmaf(fb, w0.y, aB0.y);
            aB0.z = fmaf(fb, w0.z, aB0.z); aB0.w = fmaf(fb, w0.w, aB0.w);
            aB1.x = fmaf(fb, w1.x, aB1.x); aB1.y = fmaf(fb, w1.y, aB1.y);
            aB1.z = fmaf(fb, w1.z, aB1.z); aB1.w = fmaf(fb, w1.w, aB1.w);
            aB2.x = fmaf(fb, w2.x, aB2.x); aB2.y = fmaf(fb, w2.y, aB2.y);
            aB2.z = fmaf(fb, w2.z, aB2.z); aB2.w = fmaf(fb, w2.w, aB2.w);
        }
#pragma unroll
        for (int k = 0; k < H; k++) {
            float hkA = (k % 3 == 0) ? hA0 : (k % 3 == 1) ? hA1 : hA2;
            float hkB = (k % 3 == 0) ? hB0 : (k % 3 == 1) ? hB1 : hB2;
            float fa = __shfl_sync(0xffffffffu, hkA, k / 3, 8);
            float fb = __shfl_sync(0xffffffffu, hkB, k / 3, 8);
            float4 w0 = sHp[k * 24 + j0];
            float4 w1 = sHp[k * 24 + j0 + 1];
            float4 w2 = sHp[k * 24 + j0 + 2];
            aA0.x = fmaf(fa, w0.x, aA0.x); aA0.y = fmaf(fa, w0.y, aA0.y);
            aA0.z = fmaf(fa, w0.z, aA0.z); aA0.w = fmaf(fa, w0.w, aA0.w);
            aA1.x = fmaf(fa, w1.x, aA1.x); aA1.y = fmaf(fa, w1.y, aA1.y);
            aA1.z = fmaf(fa, w1.z, aA1.z); aA1.w = fmaf(fa, w1.w, aA1.w);
            aA2.x = fmaf(fa, w2.x, aA2.x); aA2.y = fmaf(fa, w2.y, aA2.y);
            aA2.z = fmaf(fa, w2.z, aA2.z); aA2.w = fmaf(fa, w2.w, aA2.w);
            aB0.x = fmaf(fb, w0.x, aB0.x); aB0.y = fmaf(fb, w0.y, aB0.y);
            aB0.z = fmaf(fb, w0.z, aB0.z); aB0.w = fmaf(fb, w0.w, aB0.w);
            aB1.x = fmaf(fb, w1.x, aB1.x); aB1.y = fmaf(fb, w1.y, aB1.y);
            aB1.z = fmaf(fb, w1.z, aB1.z); aB1.w = fmaf(fb, w1.w, aB1.w);
            aB2.x = fmaf(fb, w2.x, aB2.x); aB2.y = fmaf(fb, w2.y, aB2.y);
            aB2.z = fmaf(fb, w2.z, aB2.z); aB2.w = fmaf(fb, w2.w, aB2.w);
        }
        {
            float gi = sigf(aA0.x), gf = sigf(aA0.y), gg = tanhfast(aA0.z), go = sigf(aA0.w);
            cA0 = gf * cA0 + gi * gg;  hA0 = go * tanhfast(cA0);
            gi = sigf(aA1.x); gf = sigf(aA1.y); gg = tanhfast(aA1.z); go = sigf(aA1.w);
            cA1 = gf * cA1 + gi * gg;  hA1 = go * tanhfast(cA1);
            gi = sigf(aA2.x); gf = sigf(aA2.y); gg = tanhfast(aA2.z); go = sigf(aA2.w);
            cA2 = gf * cA2 + gi * gg;  hA2 = go * tanhfast(cA2);
            gi = sigf(aB0.x); gf = sigf(aB0.y); gg = tanhfast(aB0.z); go = sigf(aB0.w);
            cB0 = gf * cB0 + gi * gg;  hB0 = go * tanhfast(cB0);
            gi = sigf(aB1.x); gf = sigf(aB1.y); gg = tanhfast(aB1.z); go = sigf(aB1.w);
            cB1 = gf * cB1 + gi * gg;  hB1 = go * tanhfast(cB1);
            gi = sigf(aB2.x); gf = sigf(aB2.y); gg = tanhfast(aB2.z); go = sigf(aB2.w);
            cB2 = gf * cB2 + gi * gg;  hB2 = go * tanhfast(cB2);
        }
    }

    // --- head, one sample at a time (registers reused) ---
#pragma unroll 1
    for (int smp = 0; smp < 2; smp++) {
        unsigned b = (smp == 0) ? b0 : b1;
        const float* fl = g_xsp + (size_t)b * 1080;

        float comb[36];
#pragma unroll
        for (int k = 0; k < 24; k++) {
            float hk;
            if (smp == 0) hk = (k % 3 == 0) ? hA0 : (k % 3 == 1) ? hA1 : hA2;
            else          hk = (k % 3 == 0) ? hB0 : (k % 3 == 1) ? hB1 : hB2;
            comb[k] = __shfl_sync(0xffffffffu, hk, k / 3, 8);
        }

        float pv[12];
#pragma unroll
        for (int i = 0; i < 12; i++) pv[i] = 0.f;
        const float4* x4 = reinterpret_cast<const float4*>(fl);
#pragma unroll 1
        for (int s = lane; s < 90; s += 8) {
            float4 q0 = __ldg(x4 + s * 3);
            float4 q1 = __ldg(x4 + s * 3 + 1);
            float4 q2 = __ldg(x4 + s * 3 + 2);
            pv[0] += q0.x; pv[1] += q0.y; pv[2]  += q0.z; pv[3]  += q0.w;
            pv[4] += q1.x; pv[5] += q1.y; pv[6]  += q1.z; pv[7]  += q1.w;
            pv[8] += q2.x; pv[9] += q2.y; pv[10] += q2.z; pv[11] += q2.w;
        }
#pragma unroll
        for (int i = 0; i < 12; i++) {
            float v = pv[i];
            v += __shfl_xor_sync(0xffffffffu, v, 1, 8);
            v += __shfl_xor_sync(0xffffffffu, v, 2, 8);
            v += __shfl_xor_sync(0xffffffffu, v, 4, 8);
            comb[24 + i] = v * (1.f / 90.f);
        }

        float z1[12];
#pragma unroll
        for (int i = 0; i < 12; i++) {
            float a = s_rtb1[i];
#pragma unroll
            for (int k = 0; k < 36; k++) a = fmaf(s_rtw1[i * 36 + k], comb[k], a);
            z1[i] = fmaxf(a, 0.f);
        }
        float z2[2];
#pragma unroll
        for (int i = 0; i < 2; i++) {
            float a = s_rtb2[i];
#pragma unroll
            for (int k = 0; k < 12; k++) a = fmaf(s_rtw2[i * 12 + k], z1[k], a);
            z2[i] = a;
        }
        float mx = fmaxf(z2[0], z2[1]);
        float e0 = __expf(z2[0] - mx), e1 = __expf(z2[1] - mx);
        float inv = 1.f / (e0 + e1);
        float rw0 = 0.7f * (e0 * inv), rw1 = 0.3f * (e1 * inv);
        float alpha = rw0 / (rw0 + rw1);
        float om = 1.f - alpha;

        float fin[36];
#pragma unroll
        for (int j = 0; j < 24; j++) fin[j] = comb[j] * alpha;
#pragma unroll
        for (int i = 0; i < 12; i++) fin[24 + i] = comb[24 + i] * om;

        float fused[24];
#pragma unroll
        for (int i = 0; i < 24; i++) {
            float a = s_fb[i];
#pragma unroll
            for (int k = 0; k < 36; k++) a = fmaf(s_fw[i * 36 + k], fin[k], a);
            fused[i] = fmaxf(a, 0.f);
        }
        float y1[12];
#pragma unroll
        for (int i = 0; i < 12; i++) {
            float a = s_cb1[i];
#pragma unroll
            for (int k = 0; k < 24; k++) a = fmaf(s_cw1[i * 24 + k], fused[k], a);
            y1[i] = fmaxf(a, 0.f);
        }
        if (lane == 0) {
            float* ob = out + (size_t)b * 5;
#pragma unroll
            for (int i = 0; i < 5; i++) {
                float a = s_cb2[i];
#pragma unroll
                for (int k = 0; k < 12; k++) a = fmaf(s_cw2[i * 12 + k], y1[k], a);
                ob[i] = a;
            }
        }
    }
}

extern "C" void kernel_launch(void* const* d_in, const int* in_sizes, int n_in,
                              void* d_out, int out_size) {
    const float* x   = (const float*)d_in[0];
    const float* c1w = (const float*)d_in[1];
    const float* c1b = (const float*)d_in[2];
    const float* b1g = (const float*)d_in[3];
    const float* b1b = (const float*)d_in[4];
    const float* b1m = (const float*)d_in[5];
    const float* b1v = (const float*)d_in[6];
    const float* c2w = (const float*)d_in[7];
    const float* c2b = (const float*)d_in[8];
    const float* b2g = (const float*)d_in[9];
    const float* b2b = (const float*)d_in[10];
    const float* b2m = (const float*)d_in[11];
    const float* b2v = (const float*)d_in[12];
    const float* wih = (const float*)d_in[13];
    const float* whh = (const float*)d_in[14];
    const float* bih = (const float*)d_in[15];
    const float* bhh = (const float*)d_in[16];
    const float* rtw1 = (const float*)d_in[17];
    const float* rtb1 = (const float*)d_in[18];
    const float* rtw2 = (const float*)d_in[19];
    const float* rtb2 = (const float*)d_in[20];
    const float* fw  = (const float*)d_in[21];
    const float* fb  = (const float*)d_in[22];
    const float* cw1 = (const float*)d_in[23];
    const float* cb1 = (const float*)d_in[24];
    const float* cw2 = (const float*)d_in[25];
    const float* cb2 = (const float*)d_in[26];
    float* out = (float*)d_out;

    // B*90 = 5,898,240 threads -> exactly 23040 blocks of 256
    conv_kernel<<<23040, 256>>>(x, c1w, c1b, b1g, b1b, b1m, b1v,
                                c2w, c2b, b2g, b2b, b2m, b2v);
    // B*8 threads -> 2048 blocks of 256
    lif_kernel<<<2048, 256>>>();
    // B/2 groups * 8 lanes -> 1024 blocks of 256
    lstm_head_kernel<<<1024, 256>>>(wih, whh, bih, bhh,
                                    rtw1, rtb1, rtw2, rtb2,
                                    fw, fb, cw1, cb1, cw2, cb2, out);
}

// round 11
// speedup vs baseline: 1.8962x; 1.0227x over previous
#include <cuda_runtime.h>

#define BATCH 65536
#define TSTEPS 32
#define F 33
#define H 24

// Scratch for x_spatial [B, 90, 12] (row-major, contiguous per sample).
__device__ __align__(16) float g_xsp[(size_t)BATCH * 1080];
// Spike mask per (sample, timestep): bit k = spike2[k] at step t.
__device__ __align__(16) unsigned long long g_mask[(size_t)BATCH * TSTEPS];

// ---------------------------------------------------------------------------
// Kernel A: conv1+bn1+relu -> conv2+bn2+relu -> x_spatial[b][s][c].
// One thread per (b, s); output written as 3x STG.128.
// ---------------------------------------------------------------------------
__global__ __launch_bounds__(256) void conv_kernel(
    const float* __restrict__ x,
    const float* __restrict__ w1, const float* __restrict__ cb1,
    const float* __restrict__ g1, const float* __restrict__ bb1,
    const float* __restrict__ m1, const float* __restrict__ v1,
    const float* __restrict__ w2, const float* __restrict__ cb2,
    const float* __restrict__ g2, const float* __restrict__ bb2,
    const float* __restrict__ m2, const float* __restrict__ v2)
{
    __shared__ float sw1[30], sw2[216], ss1[6], sbe1[6], ss2[12], sbe2[12];
    int tx = threadIdx.x;
    if (tx < 30)  sw1[tx] = w1[tx];
    if (tx < 216) sw2[tx] = w2[tx];
    if (tx < 6) {
        float sc = g1[tx] * rsqrtf(v1[tx] + 1e-5f);
        ss1[tx]  = sc;
        sbe1[tx] = bb1[tx] + sc * (cb1[tx] - m1[tx]);
    }
    if (tx >= 32 && tx < 44) {
        int c = tx - 32;
        float sc = g2[c] * rsqrtf(v2[c] + 1e-5f);
        ss2[c]  = sc;
        sbe2[c] = bb2[c] + sc * (cb2[c] - m2[c]);
    }
    __syncthreads();

    unsigned gid = blockIdx.x * 256u + (unsigned)tx;   // 0 .. B*90-1 (exact)
    unsigned b = gid / 90u;
    int s = (int)(gid % 90u);

    const float* xb = x + (size_t)b * 360;
    float xv[9];
    int base = 4 * s - 4;
#pragma unroll
    for (int i = 0; i < 9; i++) {
        int idx = base + i;
        xv[i] = (idx >= 0 && idx < 360) ? __ldg(xb + idx) : 0.f;
    }

    float h1v[6][3];
#pragma unroll
    for (int q = 0; q < 3; q++) {
        bool valid = (2 * s - 1 + q) >= 0;
#pragma unroll
        for (int c = 0; c < 6; c++) {
            float a = 0.f;
#pragma unroll
            for (int k = 0; k < 5; k++) a = fmaf(sw1[c * 5 + k], xv[2 * q + k], a);
            a = ss1[c] * a + sbe1[c];
            h1v[c][q] = valid ? fmaxf(a, 0.f) : 0.f;
        }
    }

    float ov[12];
#pragma unroll
    for (int c2 = 0; c2 < 12; c2++) {
        float a = 0.f;
#pragma unroll
        for (int c1 = 0; c1 < 6; c1++)
#pragma unroll
            for (int q = 0; q < 3; q++)
                a = fmaf(sw2[(c2 * 6 + c1) * 3 + q], h1v[c1][q], a);
        a = ss2[c2] * a + sbe2[c2];
        ov[c2] = fmaxf(a, 0.f);
    }
    float4* o4 = reinterpret_cast<float4*>(g_xsp + (size_t)b * 1080 + s * 12);
    o4[0] = make_float4(ov[0], ov[1], ov[2],  ov[3]);
    o4[1] = make_float4(ov[4], ov[5], ov[6],  ov[7]);
    o4[2] = make_float4(ov[8], ov[9], ov[10], ov[11]);
}

// ---------------------------------------------------------------------------
// Kernel B: double LIF, 8 lanes per sample (lane owns k = lane+8i).
// Emits per-(b,t) 33-bit spike mask as uint64.
// ---------------------------------------------------------------------------
__global__ __launch_bounds__(256) void lif_kernel()
{
    unsigned gtid = blockIdx.x * 256u + threadIdx.x;   // B*8 threads
    unsigned b = gtid >> 3;
    int lane = threadIdx.x & 7;
    const float* fl = g_xsp + (size_t)b * 1080;

    float mem1[5], mem2[5];
#pragma unroll
    for (int i = 0; i < 5; i++) { mem1[i] = 0.f; mem2[i] = 0.f; }

#pragma unroll 1
    for (int t = 0; t < TSTEPS; t++) {
        const float* xt = fl + t * F;
        unsigned long long pm = 0ull;
#pragma unroll
        for (int i = 0; i < 5; i++) {
            if (i < 4 || lane == 0) {           // k = lane + 8i < 33
                int k = lane + 8 * i;
                float in = __ldg(xt + k);
                float a = 0.95f * mem1[i] + in;
                float s1 = (a > 0.5f) ? 1.f : 0.f;
                mem1[i] = a * (1.f - s1);
                float bm = 0.9f * mem2[i] + s1;
                if (bm > 0.6f) { pm |= (1ull << k); mem2[i] = 0.f; }
                else mem2[i] = bm;
            }
        }
        pm |= __shfl_xor_sync(0xffffffffu, pm, 1, 8);
        pm |= __shfl_xor_sync(0xffffffffu, pm, 2, 8);
        pm |= __shfl_xor_sync(0xffffffffu, pm, 4, 8);
        if (lane == 0) g_mask[(size_t)b * TSTEPS + t] = pm;
    }
}

// ---------------------------------------------------------------------------
// Kernel C: LSTM + head. 8 lanes x 4 samples per thread.
// Lane owns hidden units j0..j0+2 of all four samples.
// ---------------------------------------------------------------------------
__device__ __forceinline__ float sigf(float x) {
    return __fdividef(1.f, 1.f + __expf(-x));
}
__device__ __forceinline__ float tanhfast(float x) {
    float e = __expf(2.f * x);
    return 1.f - __fdividef(2.f, e + 1.f);   // correct limits at +/-inf
}

#define NS 4   // samples per thread

__global__ __launch_bounds__(256) void lstm_head_kernel(
    const float* __restrict__ wih, const float* __restrict__ whh,
    const float* __restrict__ bih, const float* __restrict__ bhh,
    const float* __restrict__ rtw1, const float* __restrict__ rtb1,
    const float* __restrict__ rtw2, const float* __restrict__ rtb2,
    const float* __restrict__ fw,  const float* __restrict__ fb,
    const float* __restrict__ cw1, const float* __restrict__ cb1_,
    const float* __restrict__ cw2, const float* __restrict__ cb2_,
    float* __restrict__ out)
{
    __shared__ float4 sWp[F * 24];     // {Wi,Wf,Wg,Wo}[k][j]
    __shared__ float4 sHp[24 * 24];
    __shared__ float4 sBs[24];
    __shared__ float s_rtw1[12 * 36], s_rtb1[12], s_rtw2[24], s_rtb2[2];
    __shared__ float s_fw[24 * 36], s_fb[24];
    __shared__ float s_cw1[12 * 24], s_cb1[12], s_cw2[60], s_cb2[5];

    int tx = threadIdx.x;
    for (int i = tx; i < F * 24; i += 256) {
        int k = i / 24, j = i % 24;
        sWp[i] = make_float4(wih[j * F + k], wih[(24 + j) * F + k],
                             wih[(48 + j) * F + k], wih[(72 + j) * F + k]);
    }
    for (int i = tx; i < 24 * 24; i += 256) {
        int k = i / 24, j = i % 24;
        sHp[i] = make_float4(whh[j * 24 + k], whh[(24 + j) * 24 + k],
                             whh[(48 + j) * 24 + k], whh[(72 + j) * 24 + k]);
    }
    if (tx < 24)
        sBs[tx] = make_float4(bih[tx] + bhh[tx], bih[24 + tx] + bhh[24 + tx],
                              bih[48 + tx] + bhh[48 + tx], bih[72 + tx] + bhh[72 + tx]);
    for (int i = tx; i < 432; i += 256) s_rtw1[i] = rtw1[i];
    if (tx < 12) s_rtb1[tx] = rtb1[tx];
    if (tx < 24) s_rtw2[tx] = rtw2[tx];
    if (tx < 2)  s_rtb2[tx] = rtb2[tx];
    for (int i = tx; i < 864; i += 256) s_fw[i] = fw[i];
    if (tx < 24) s_fb[tx] = fb[tx];
    for (int i = tx; i < 288; i += 256) s_cw1[i] = cw1[i];
    if (tx < 12) s_cb1[tx] = cb1_[tx];
    if (tx < 60) s_cw2[tx] = cw2[tx];
    if (tx < 5)  s_cb2[tx] = cb2_[tx];
    __syncthreads();

    unsigned gtid = blockIdx.x * 256u + (unsigned)tx;
    unsigned grp = gtid >> 3;          // 8 lanes per group of NS samples
    int lane = tx & 7;
    int j0 = lane * 3;
    unsigned bb = grp * NS;

    float hs[NS][3], cs[NS][3];
#pragma unroll
    for (int s = 0; s < NS; s++)
#pragma unroll
        for (int u = 0; u < 3; u++) { hs[s][u] = 0.f; cs[s][u] = 0.f; }

#pragma unroll 1
    for (int t = 0; t < TSTEPS; t++) {
        unsigned long long mk[NS];
#pragma unroll
        for (int s = 0; s < NS; s++)
            mk[s] = __ldg(&g_mask[(size_t)(bb + s) * TSTEPS + t]);

        float4 acc[NS][3];
        {
            float4 b0 = sBs[j0], b1 = sBs[j0 + 1], b2 = sBs[j0 + 2];
#pragma unroll
            for (int s = 0; s < NS; s++) {
                acc[s][0] = b0; acc[s][1] = b1; acc[s][2] = b2;
            }
        }
#pragma unroll
        for (int k = 0; k < F; k++) {
            float4 w0 = sWp[k * 24 + j0];
            float4 w1 = sWp[k * 24 + j0 + 1];
            float4 w2 = sWp[k * 24 + j0 + 2];
#pragma unroll
            for (int s = 0; s < NS; s++) {
                float f = (float)((unsigned)(mk[s] >> k) & 1u);
                acc[s][0].x = fmaf(f, w0.x, acc[s][0].x);
                acc[s][0].y = fmaf(f, w0.y, acc[s][0].y);
                acc[s][0].z = fmaf(f, w0.z, acc[s][0].z);
                acc[s][0].w = fmaf(f, w0.w, acc[s][0].w);
                acc[s][1].x = fmaf(f, w1.x, acc[s][1].x);
                acc[s][1].y = fmaf(f, w1.y, acc[s][1].y);
                acc[s][1].z = fmaf(f, w1.z, acc[s][1].z);
                acc[s][1].w = fmaf(f, w1.w, acc[s][1].w);
                acc[s][2].x = fmaf(f, w2.x, acc[s][2].x);
                acc[s][2].y = fmaf(f, w2.y, acc[s][2].y);
                acc[s][2].z = fmaf(f, w2.z, acc[s][2].z);
                acc[s][2].w = fmaf(f, w2.w, acc[s][2].w);
            }
        }
#pragma unroll
        for (int k = 0; k < H; k++) {
            float4 w0 = sHp[k * 24 + j0];
            float4 w1 = sHp[k * 24 + j0 + 1];
            float4 w2 = sHp[k * 24 + j0 + 2];
#pragma unroll
            for (int s = 0; s < NS; s++) {
                float hk = hs[s][k % 3];
                float f = __shfl_sync(0xffffffffu, hk, k / 3, 8);
                acc[s][0].x = fmaf(f, w0.x, acc[s][0].x);
                acc[s][0].y = fmaf(f, w0.y, acc[s][0].y);
                acc[s][0].z = fmaf(f, w0.z, acc[s][0].z);
                acc[s][0].w = fmaf(f, w0.w, acc[s][0].w);
                acc[s][1].x = fmaf(f, w1.x, acc[s][1].x);
                acc[s][1].y = fmaf(f, w1.y, acc[s][1].y);
                acc[s][1].z = fmaf(f, w1.z, acc[s][1].z);
                acc[s][1].w = fmaf(f, w1.w, acc[s][1].w);
                acc[s][2].x = fmaf(f, w2.x, acc[s][2].x);
                acc[s][2].y = fmaf(f, w2.y, acc[s][2].y);
                acc[s][2].z = fmaf(f, w2.z, acc[s][2].z);
                acc[s][2].w = fmaf(f, w2.w, acc[s][2].w);
            }
        }
#pragma unroll
        for (int s = 0; s < NS; s++) {
#pragma unroll
            for (int u = 0; u < 3; u++) {
                float gi = sigf(acc[s][u].x);
                float gf = sigf(acc[s][u].y);
                float gg = tanhfast(acc[s][u].z);
                float go = sigf(acc[s][u].w);
                cs[s][u] = gf * cs[s][u] + gi * gg;
                hs[s][u] = go * tanhfast(cs[s][u]);
            }
        }
    }

    // --- head, one sample at a time (registers reused) ---
#pragma unroll 1
    for (int smp = 0; smp < NS; smp++) {
        unsigned b = bb + smp;
        const float* fl = g_xsp + (size_t)b * 1080;

        float comb[36];
#pragma unroll
        for (int k = 0; k < 24; k++) {
            float hk = hs[smp][k % 3];
            comb[k] = __shfl_sync(0xffffffffu, hk, k / 3, 8);
        }

        float pv[12];
#pragma unroll
        for (int i = 0; i < 12; i++) pv[i] = 0.f;
        const float4* x4 = reinterpret_cast<const float4*>(fl);
#pragma unroll 1
        for (int s = lane; s < 90; s += 8) {
            float4 q0 = __ldg(x4 + s * 3);
            float4 q1 = __ldg(x4 + s * 3 + 1);
            float4 q2 = __ldg(x4 + s * 3 + 2);
            pv[0] += q0.x; pv[1] += q0.y; pv[2]  += q0.z; pv[3]  += q0.w;
            pv[4] += q1.x; pv[5] += q1.y; pv[6]  += q1.z; pv[7]  += q1.w;
            pv[8] += q2.x; pv[9] += q2.y; pv[10] += q2.z; pv[11] += q2.w;
        }
#pragma unroll
        for (int i = 0; i < 12; i++) {
            float v = pv[i];
            v += __shfl_xor_sync(0xffffffffu, v, 1, 8);
            v += __shfl_xor_sync(0xffffffffu, v, 2, 8);
            v += __shfl_xor_sync(0xffffffffu, v, 4, 8);
            comb[24 + i] = v * (1.f / 90.f);
        }

        float z1[12];
#pragma unroll
        for (int i = 0; i < 12; i++) {
            float a = s_rtb1[i];
#pragma unroll
            for (int k = 0; k < 36; k++) a = fmaf(s_rtw1[i * 36 + k], comb[k], a);
            z1[i] = fmaxf(a, 0.f);
        }
        float z2[2];
#pragma unroll
        for (int i = 0; i < 2; i++) {
            float a = s_rtb2[i];
#pragma unroll
            for (int k = 0; k < 12; k++) a = fmaf(s_rtw2[i * 12 + k], z1[k], a);
            z2[i] = a;
        }
        float mx = fmaxf(z2[0], z2[1]);
        float e0 = __expf(z2[0] - mx), e1 = __expf(z2[1] - mx);
        float inv = 1.f / (e0 + e1);
        float rw0 = 0.7f * (e0 * inv), rw1 = 0.3f * (e1 * inv);
        float alpha = rw0 / (rw0 + rw1);
        float om = 1.f - alpha;

        float fin[36];
#pragma unroll
        for (int j = 0; j < 24; j++) fin[j] = comb[j] * alpha;
#pragma unroll
        for (int i = 0; i < 12; i++) fin[24 + i] = comb[24 + i] * om;

        float fused[24];
#pragma unroll
        for (int i = 0; i < 24; i++) {
            float a = s_fb[i];
#pragma unroll
            for (int k = 0; k < 36; k++) a = fmaf(s_fw[i * 36 + k], fin[k], a);
            fused[i] = fmaxf(a, 0.f);
        }
        float y1[12];
#pragma unroll
        for (int i = 0; i < 12; i++) {
            float a = s_cb1[i];
#pragma unroll
            for (int k = 0; k < 24; k++) a = fmaf(s_cw1[i * 24 + k], fused[k], a);
            y1[i] = fmaxf(a, 0.f);
        }
        if (lane == 0) {
            float* ob = out + (size_t)b * 5;
#pragma unroll
            for (int i = 0; i < 5; i++) {
                float a = s_cb2[i];
#pragma unroll
                for (int k = 0; k < 12; k++) a = fmaf(s_cw2[i * 12 + k], y1[k], a);
                ob[i] = a;
            }
        }
    }
}

extern "C" void kernel_launch(void* const* d_in, const int* in_sizes, int n_in,
                              void* d_out, int out_size) {
    const float* x   = (const float*)d_in[0];
    const float* c1w = (const float*)d_in[1];
    const float* c1b = (const float*)d_in[2];
    const float* b1g = (const float*)d_in[3];
    const float* b1b = (const float*)d_in[4];
    const float* b1m = (const float*)d_in[5];
    const float* b1v = (const float*)d_in[6];
    const float* c2w = (const float*)d_in[7];
    const float* c2b = (const float*)d_in[8];
    const float* b2g = (const float*)d_in[9];
    const float* b2b = (const float*)d_in[10];
    const float* b2m = (const float*)d_in[11];
    const float* b2v = (const float*)d_in[12];
    const float* wih = (const float*)d_in[13];
    const float* whh = (const float*)d_in[14];
    const float* bih = (const float*)d_in[15];
    const float* bhh = (const float*)d_in[16];
    const float* rtw1 = (const float*)d_in[17];
    const float* rtb1 = (const float*)d_in[18];
    const float* rtw2 = (const float*)d_in[19];
    const float* rtb2 = (const float*)d_in[20];
    const float* fw  = (const float*)d_in[21];
    const float* fb  = (const float*)d_in[22];
    const float* cw1 = (const float*)d_in[23];
    const float* cb1 = (const float*)d_in[24];
    const float* cw2 = (const float*)d_in[25];
    const float* cb2 = (const float*)d_in[26];
    float* out = (float*)d_out;

    // B*90 = 5,898,240 threads -> exactly 23040 blocks of 256
    conv_kernel<<<23040, 256>>>(x, c1w, c1b, b1g, b1b, b1m, b1v,
                                c2w, c2b, b2g, b2b, b2m, b2v);
    // B*8 threads -> 2048 blocks of 256
    lif_kernel<<<2048, 256>>>();
    // (B/4) groups * 8 lanes = 131072 threads -> 512 blocks of 256
    lstm_head_kernel<<<512, 256>>>(wih, whh, bih, bhh,
                                   rtw1, rtb1, rtw2, rtb2,
                                   fw, fb, cw1, cb1, cw2, cb2, out);
}